// round 1
// baseline (speedup 1.0000x reference)
#include <cuda_runtime.h>
#include <cuda_bf16.h>

// Problem constants
#define S_LEN   5000
#define BATCH   64
#define EMB     128
#define EMB4    (EMB/4)            // 32 float4 per row

// Output layout: [NFEs | PFEs | visited_time] flattened, all as float32
#define NFE_OFF 0
#define PFE_OFF ((size_t)BATCH * S_LEN * EMB)          // 40,960,000
#define VT_OFF  ((size_t)2 * BATCH * S_LEN * EMB)      // 81,920,000

#define CHASE_PER_BATCH 2
#define CHASE_BLOCKS    (BATCH * CHASE_PER_BATCH)      // 128
#define NFE_BLOCKS      160
#define TOTAL_BLOCKS    (CHASE_BLOCKS + NFE_BLOCKS)    // 288
#define THREADS         1024

#define NULL16 0xFFFFu

__global__ __launch_bounds__(THREADS, 2)
void embeddingnet_fused(const float* __restrict__ x,
                        const float* __restrict__ W,
                        const float* __restrict__ pattern,
                        const int*   __restrict__ sol,
                        float*       __restrict__ out)
{
    const int bid = blockIdx.x;

    if (bid < CHASE_BLOCKS) {
        // ---------------- Wyllie list-ranking + PFE gather ----------------
        // Packed state per node v: (next:16 | rank:16). next==NULL16 means
        // the chain has reached node 0; rank then holds distance(v -> 0).
        __shared__ unsigned bufA[S_LEN];
        __shared__ unsigned bufB[S_LEN];

        const int b    = bid / CHASE_PER_BATCH;
        const int part = bid % CHASE_PER_BATCH;
        const int t    = threadIdx.x;
        const int* __restrict__ srow = sol + (size_t)b * S_LEN;

        // init: next = succ(v) (NULL if succ==0), rank = 1
        for (int v = t; v < S_LEN; v += THREADS) {
            unsigned s = (unsigned)srow[v];
            unsigned n = (s == 0u) ? NULL16 : s;
            bufA[v] = (n << 16) | 1u;
        }
        __syncthreads();

        unsigned* rd = bufA;
        unsigned* wr = bufB;
        // 13 rounds: 2^13 = 8192 >= 5000 covers the full chain
        #pragma unroll 1
        for (int it = 0; it < 13; ++it) {
            for (int v = t; v < S_LEN; v += THREADS) {
                unsigned c = rd[v];
                unsigned n = c >> 16;
                if (n != NULL16) {
                    unsigned cn = rd[n];
                    // new next = next(next); new rank = rank + rank(next)
                    c = (cn & 0xFFFF0000u) | ((c + cn) & 0xFFFFu);
                }
                wr[v] = c;
            }
            __syncthreads();
            unsigned* tmp = rd; rd = wr; wr = tmp;
        }

        // idx(v) = visited_time(v) % S = S - r(v)   (r(0) = S -> idx 0)
        // visited_time(v) = idx(v) except v==0 where it is S.
        float* out_vt = out + VT_OFF + (size_t)b * S_LEN;
        for (int v = t; v < S_LEN; v += THREADS) {
            int r   = (int)(rd[v] & 0xFFFFu);
            int idx = S_LEN - r;
            if (part == 0)
                out_vt[v] = (float)((v == 0) ? S_LEN : idx);
            wr[v] = (unsigned)idx;     // stash idx for the gather phase
        }
        __syncthreads();

        // PFE gather: this block writes rows [r0, r1) of batch b
        float4* __restrict__ pfe = (float4*)(out + PFE_OFF + (size_t)b * S_LEN * EMB);
        const float4* __restrict__ pat4 = (const float4*)pattern;
        const int rows_per = (S_LEN + CHASE_PER_BATCH - 1) / CHASE_PER_BATCH;
        const int r0 = part * rows_per;
        const int r1 = (r0 + rows_per < S_LEN) ? (r0 + rows_per) : S_LEN;
        const int nunits = (r1 - r0) * EMB4;

        for (int u = t; u < nunits; u += THREADS) {
            int v = r0 + u / EMB4;
            int c = u % EMB4;
            pfe[(size_t)v * EMB4 + c] = pat4[(size_t)wr[v] * EMB4 + c];
        }
    } else {
        // ---------------- NFE: out[b,s,d] = x[b,s,0]*W[d,0] + x[b,s,1]*W[d,1]
        const int nb = bid - CHASE_BLOCKS;
        const long total = (long)BATCH * S_LEN * EMB4;   // float4 units
        float4* __restrict__ nfe = (float4*)(out + NFE_OFF);
        const float2* __restrict__ x2 = (const float2*)x;
        const float4* __restrict__ W4 = (const float4*)W;

        for (long u = (long)nb * THREADS + threadIdx.x; u < total;
             u += (long)NFE_BLOCKS * THREADS) {
            long row = u >> 5;            // / EMB4
            int  c4  = (int)(u & 31);     // % EMB4
            float2 xv = x2[row];
            // W row-major [128,2]: float4 pair covers d = 4*c4 .. 4*c4+3
            float4 wlo = W4[c4 * 2];
            float4 whi = W4[c4 * 2 + 1];
            float4 o;
            o.x = xv.x * wlo.x + xv.y * wlo.y;
            o.y = xv.x * wlo.z + xv.y * wlo.w;
            o.z = xv.x * whi.x + xv.y * whi.y;
            o.w = xv.x * whi.z + xv.y * whi.w;
            nfe[u] = o;
        }
    }
}

extern "C" void kernel_launch(void* const* d_in, const int* in_sizes, int n_in,
                              void* d_out, int out_size)
{
    const float* x       = (const float*)d_in[0];   // [64,5000,2]
    const float* W       = (const float*)d_in[1];   // [128,2]
    const float* pattern = (const float*)d_in[2];   // [5000,128]
    const int*   sol     = (const int*)  d_in[3];   // [64,5000]
    float* out = (float*)d_out;

    embeddingnet_fused<<<TOTAL_BLOCKS, THREADS>>>(x, W, pattern, sol, out);
}

// round 2
// speedup vs baseline: 1.0061x; 1.0061x over previous
#include <cuda_runtime.h>
#include <cuda_bf16.h>

// Problem constants
#define S_LEN   5000
#define BATCH   64
#define EMB     128
#define EMB4    32                 // float4 per row

// Output layout: [NFEs | PFEs | visited_time] flattened, all as float32
#define NFE_OFF 0
#define PFE_OFF ((size_t)BATCH * S_LEN * EMB)          // 40,960,000
#define VT_OFF  ((size_t)2 * BATCH * S_LEN * EMB)      // 81,920,000

#define THREADS        1024
#define CHASE_BLOCKS   64
#define TOTAL_BLOCKS   288

// Dynamic work pool: 128KB chunks
#define NFE_UNITS        10240000L                 // BATCH*S_LEN*EMB4 float4 units
#define CHUNK_UNITS      8192                      // 8192 float4 = 128KB
#define NFE_CHUNKS       1250                      // NFE_UNITS / CHUNK_UNITS (exact)
#define PFE_ROWS_CHUNK   256                       // 256 rows * 512B = 128KB
#define PFE_CHUNKS_PER_B 20                        // ceil(5000/256)
#define PFE_CHUNKS       (BATCH * PFE_CHUNKS_PER_B)
#define TOTAL_CHUNKS     (NFE_CHUNKS + PFE_CHUNKS)

#define NULL16 0xFFFFu

// Persistent scratch (no allocations allowed)
__device__ unsigned       g_counter;
__device__ int            g_ready[BATCH];
__device__ unsigned short g_idx[BATCH * S_LEN];

__global__ void init_pool() {
    if (threadIdx.x == 0) g_counter = 0u;
    if (threadIdx.x < BATCH) g_ready[threadIdx.x] = 0;
}

__global__ __launch_bounds__(THREADS, 2)
void embeddingnet_fused(const float* __restrict__ x,
                        const float* __restrict__ W,
                        const float* __restrict__ pattern,
                        const int*   __restrict__ sol,
                        float*       __restrict__ out)
{
    __shared__ unsigned bufA[S_LEN];
    __shared__ unsigned bufB[S_LEN];
    __shared__ unsigned s_chunk;

    const int bid = blockIdx.x;
    const int t   = threadIdx.x;

    // ============ Phase 1 (blocks 0..63): Wyllie list-ranking ============
    if (bid < CHASE_BLOCKS) {
        const int b = bid;
        const int* __restrict__ srow = sol + (size_t)b * S_LEN;

        // Packed state per node v: (next:16 | rank:16). next==NULL16 means
        // the chain has reached node 0; rank then holds distance(v -> 0).
        for (int v = t; v < S_LEN; v += THREADS) {
            unsigned s = (unsigned)srow[v];
            unsigned n = (s == 0u) ? NULL16 : s;
            bufA[v] = (n << 16) | 1u;
        }
        __syncthreads();

        unsigned* rd = bufA;
        unsigned* wr = bufB;
        #pragma unroll 1
        for (int it = 0; it < 13; ++it) {          // 2^13 >= 5000
            for (int v = t; v < S_LEN; v += THREADS) {
                unsigned c = rd[v];
                unsigned n = c >> 16;
                if (n != NULL16) {
                    unsigned cn = rd[n];
                    c = (cn & 0xFFFF0000u) | ((c + cn) & 0xFFFFu);
                }
                wr[v] = c;
            }
            __syncthreads();
            unsigned* tmp = rd; rd = wr; wr = tmp;
        }

        // idx(v) = visited_time(v) % S = S - r(v);  vt(v)=idx except v==0 -> S
        float* out_vt = out + VT_OFF + (size_t)b * S_LEN;
        unsigned short* idxrow = g_idx + (size_t)b * S_LEN;
        for (int v = t; v < S_LEN; v += THREADS) {
            int r   = (int)(rd[v] & 0xFFFFu);
            int idx = S_LEN - r;
            out_vt[v] = (float)((v == 0) ? S_LEN : idx);
            idxrow[v] = (unsigned short)idx;
        }
        __syncthreads();
        if (t == 0) {
            __threadfence();                        // publish idxrow
            atomicExch(&g_ready[b], 1);             // release flag
        }
    }

    // ============ Phase 2 (all blocks): dynamic streaming pool ============
    const float2* __restrict__ x2   = (const float2*)x;
    const float4* __restrict__ W4   = (const float4*)W;
    const float4* __restrict__ pat4 = (const float4*)pattern;
    float4* __restrict__ nfe = (float4*)(out + NFE_OFF);
    float4* __restrict__ pfe_base = (float4*)(out + PFE_OFF);

    for (;;) {
        if (t == 0) s_chunk = atomicAdd(&g_counter, 1u);
        __syncthreads();
        unsigned c = s_chunk;
        if (c >= TOTAL_CHUNKS) break;

        if (c < NFE_CHUNKS) {
            // --- NFE chunk: out[b,s,d] = x[b,s,0]*W[d,0] + x[b,s,1]*W[d,1]
            long base = (long)c * CHUNK_UNITS;
            #pragma unroll
            for (int k = 0; k < 8; ++k) {
                long u   = base + t + k * THREADS;
                long row = u >> 5;
                int  c4  = (int)(u & 31);
                float2 xv  = x2[row];
                float4 wlo = W4[c4 * 2];
                float4 whi = W4[c4 * 2 + 1];
                float4 o;
                o.x = xv.x * wlo.x + xv.y * wlo.y;
                o.y = xv.x * wlo.z + xv.y * wlo.w;
                o.z = xv.x * whi.x + xv.y * whi.y;
                o.w = xv.x * whi.z + xv.y * whi.w;
                nfe[u] = o;
            }
        } else {
            // --- PFE chunk: gather pattern rows by idx for one batch segment
            int pc  = (int)(c - NFE_CHUNKS);
            int b   = pc / PFE_CHUNKS_PER_B;
            int seg = pc % PFE_CHUNKS_PER_B;

            if (t == 0) {                           // acquire producer flag
                volatile int* rf = g_ready;
                while (rf[b] == 0) { }
                __threadfence();
            }
            __syncthreads();

            int r0 = seg * PFE_ROWS_CHUNK;
            int r1 = r0 + PFE_ROWS_CHUNK; if (r1 > S_LEN) r1 = S_LEN;
            int n  = (r1 - r0) * EMB4;
            const unsigned short* __restrict__ idxrow = g_idx + (size_t)b * S_LEN;
            float4* __restrict__ pfe = pfe_base + (size_t)b * S_LEN * EMB4;

            for (int u = t; u < n; u += THREADS) {
                int v   = r0 + (u >> 5);
                int col = u & 31;
                pfe[(size_t)v * EMB4 + col] = pat4[(size_t)idxrow[v] * EMB4 + col];
            }
        }
        __syncthreads();                            // s_chunk reuse guard
    }
}

extern "C" void kernel_launch(void* const* d_in, const int* in_sizes, int n_in,
                              void* d_out, int out_size)
{
    const float* x       = (const float*)d_in[0];   // [64,5000,2]
    const float* W       = (const float*)d_in[1];   // [128,2]
    const float* pattern = (const float*)d_in[2];   // [5000,128]
    const int*   sol     = (const int*)  d_in[3];   // [64,5000]
    float* out = (float*)d_out;

    init_pool<<<1, 64>>>();
    embeddingnet_fused<<<TOTAL_BLOCKS, THREADS>>>(x, W, pattern, sol, out);
}